// round 5
// baseline (speedup 1.0000x reference)
#include <cuda_runtime.h>
#include <cuda_fp16.h>
#include <cstdint>

#define D_MODEL 1024
#define SEQ     2048
#define BATCH   4
#define NH      16
#define HD      64
#define ROWS    (BATCH*SEQ)   // 8192

// ---------------- static device scratch (no allocs allowed) ----------------
__device__ alignas(16) __half g_xh [ROWS*D_MODEL];
__device__ alignas(16) __half g_wq [D_MODEL*D_MODEL];
__device__ alignas(16) __half g_wk [D_MODEL*D_MODEL];
__device__ alignas(16) __half g_wv [D_MODEL*D_MODEL];
__device__ alignas(16) __half g_wo [D_MODEL*D_MODEL];
__device__ alignas(16) __half g_q  [ROWS*D_MODEL];   // [B,H,S,HD]
__device__ alignas(16) __half g_k  [ROWS*D_MODEL];   // [B,H,S,HD]
__device__ alignas(16) __half g_v  [ROWS*D_MODEL];   // [B,H,S,HD]
__device__ alignas(16) __half g_ctx[ROWS*D_MODEL];   // [B,S,D]

// ---------------- helpers ----------------
__device__ __forceinline__ uint32_t smem_u32(const void* p) {
    return (uint32_t)__cvta_generic_to_shared(p);
}
__device__ __forceinline__ void ldmat_x4(uint32_t& r0, uint32_t& r1, uint32_t& r2, uint32_t& r3, uint32_t addr) {
    asm volatile("ldmatrix.sync.aligned.m8n8.x4.shared.b16 {%0,%1,%2,%3}, [%4];"
                 : "=r"(r0), "=r"(r1), "=r"(r2), "=r"(r3) : "r"(addr));
}
__device__ __forceinline__ void ldmat_x4_t(uint32_t& r0, uint32_t& r1, uint32_t& r2, uint32_t& r3, uint32_t addr) {
    asm volatile("ldmatrix.sync.aligned.m8n8.x4.trans.shared.b16 {%0,%1,%2,%3}, [%4];"
                 : "=r"(r0), "=r"(r1), "=r"(r2), "=r"(r3) : "r"(addr));
}
__device__ __forceinline__ void mma16816(float* c, const uint32_t* a, uint32_t b0, uint32_t b1) {
    asm volatile("mma.sync.aligned.m16n8k16.row.col.f32.f16.f16.f32 "
                 "{%0,%1,%2,%3}, {%4,%5,%6,%7}, {%8,%9}, {%0,%1,%2,%3};"
                 : "+f"(c[0]), "+f"(c[1]), "+f"(c[2]), "+f"(c[3])
                 : "r"(a[0]), "r"(a[1]), "r"(a[2]), "r"(a[3]), "r"(b0), "r"(b1));
}
__device__ __forceinline__ void cpasync16(uint32_t saddr, const void* g) {
    asm volatile("cp.async.cg.shared.global [%0], [%1], 16;" :: "r"(saddr), "l"(g));
}
__device__ __forceinline__ void cp_commit() { asm volatile("cp.async.commit_group;"); }
template<int N> __device__ __forceinline__ void cp_wait() { asm volatile("cp.async.wait_group %0;" :: "n"(N)); }

__device__ __forceinline__ uint32_t packh2(float a, float b) {
    __half2 h = __floats2half2_rn(a, b);
    return *reinterpret_cast<uint32_t*>(&h);
}

// ---------------- fused fp32 -> fp16 convert (one launch) ----------------
#define N_X  (ROWS*D_MODEL)
#define N_W  (D_MODEL*D_MODEL)
__global__ __launch_bounds__(256) void f2h_all(
    const float* __restrict__ x,  const float* __restrict__ wq,
    const float* __restrict__ wk, const float* __restrict__ wv,
    const float* __restrict__ wo)
{
    int i = (blockIdx.x * blockDim.x + threadIdx.x) * 4;
    const float* src; __half* dst; int off;
    if (i < N_X)                { src = x;  dst = g_xh; off = 0; }
    else if (i < N_X + N_W)     { src = wq; dst = g_wq; off = N_X; }
    else if (i < N_X + 2*N_W)   { src = wk; dst = g_wk; off = N_X + N_W; }
    else if (i < N_X + 3*N_W)   { src = wv; dst = g_wv; off = N_X + 2*N_W; }
    else                        { src = wo; dst = g_wo; off = N_X + 3*N_W; }
    int j = i - off;
    float4 v = *reinterpret_cast<const float4*>(src + j);
    __half2* d2 = reinterpret_cast<__half2*>(dst + j);
    d2[0] = __floats2half2_rn(v.x, v.y);
    d2[1] = __floats2half2_rn(v.z, v.w);
}

// ---------------- GEMM core: C[128x128] = A[128xK] * W[KxN], K=N=1024 ----------------
// 3-stage cp.async pipeline, ONE __syncthreads per K-tile iteration.
#define GSA 40    // A smem row stride (halves): conflict-free for ldmatrix
#define GSB 136   // B smem row stride (halves): conflict-free
#define KTILES (D_MODEL/32)
#define NSTG 3

__device__ __forceinline__ void gemm_core(
    const __half* __restrict__ A, const __half* __restrict__ W,
    __half* As, __half* Bs, float acc[2][8][4])
{
    const int tid  = threadIdx.x;
    const int lane = tid & 31;
    const int warp = tid >> 5;
    const int wm   = warp & 3;
    const int wn   = warp >> 2;
    const int row0 = blockIdx.y * 128;
    const int col0 = blockIdx.x * 128;

#pragma unroll
    for (int im = 0; im < 2; im++)
#pragma unroll
        for (int jn = 0; jn < 8; jn++)
#pragma unroll
            for (int q = 0; q < 4; q++) acc[im][jn][q] = 0.f;

    auto loadAB = [&](int kt, int st) {
#pragma unroll
        for (int i = 0; i < 2; i++) {
            int c = tid + i * 256;
            int r = c >> 2, cc = c & 3;
            cpasync16(smem_u32(As + st * 128 * GSA + r * GSA + cc * 8),
                      A + (size_t)(row0 + r) * D_MODEL + kt * 32 + cc * 8);
        }
#pragma unroll
        for (int i = 0; i < 2; i++) {
            int c = tid + i * 256;
            int r = c >> 4, cc = c & 15;
            cpasync16(smem_u32(Bs + st * 32 * GSB + r * GSB + cc * 8),
                      W + (size_t)(kt * 32 + r) * D_MODEL + col0 + cc * 8);
        }
    };

    // prologue: stages 0,1 in flight (groups g0, g1)
    loadAB(0, 0); cp_commit();
    loadAB(1, 1); cp_commit();

    for (int kt = 0; kt < KTILES; kt++) {
        // need group kt done; exactly one newer group (kt+1) is committed -> wait<1>
        cp_wait<1>();
        __syncthreads();   // orders: stage data visible to all warps, AND all warps
                           // finished reading stage (kt-1)%3 which we write next

        if (kt + 2 < KTILES) loadAB(kt + 2, (kt + 2) % NSTG);
        cp_commit();       // unconditional: keeps group numbering uniform

        const __half* as = As + (kt % NSTG) * 128 * GSA;
        const __half* bs = Bs + (kt % NSTG) * 32 * GSB;

#pragma unroll
        for (int kk = 0; kk < 2; kk++) {
            uint32_t af[2][4];
#pragma unroll
            for (int im = 0; im < 2; im++) {
                int r    = wm * 32 + im * 16 + (lane & 15);
                int ccol = kk * 16 + (lane >> 4) * 8;
                ldmat_x4(af[im][0], af[im][1], af[im][2], af[im][3],
                         smem_u32(as + r * GSA + ccol));
            }
#pragma unroll
            for (int jp = 0; jp < 4; jp++) {
                uint32_t b0, b1, b2, b3;
                int br = kk * 16 + (lane & 7) + 8 * ((lane >> 3) & 1);
                int bc = wn * 64 + jp * 16 + 8 * (lane >> 4);
                ldmat_x4_t(b0, b1, b2, b3, smem_u32(bs + br * GSB + bc));
                mma16816(acc[0][2*jp  ], af[0], b0, b1);
                mma16816(acc[1][2*jp  ], af[1], b0, b1);
                mma16816(acc[0][2*jp+1], af[0], b2, b3);
                mma16816(acc[1][2*jp+1], af[1], b2, b3);
            }
        }
    }
}

// ---------------- QKV projection: z selects W/bias/dst ----------------
// Q gets 0.125 * log2(e) folded in so attention can use exp2 directly.
#define QSCALE 0.180336879f   // (1/sqrt(64)) * log2(e)

__global__ __launch_bounds__(256) void gemm_qkv_kernel(
    const float* __restrict__ bq, const float* __restrict__ bk, const float* __restrict__ bv)
{
    __shared__ alignas(16) __half As[NSTG * 128 * GSA];
    __shared__ alignas(16) __half Bs[NSTG * 32 * GSB];

    const __half* W; __half* dst; const float* bias; float scale;
    if      (blockIdx.z == 0) { W = g_wq; dst = g_q; bias = bq; scale = QSCALE; }
    else if (blockIdx.z == 1) { W = g_wk; dst = g_k; bias = bk; scale = 1.f; }
    else                      { W = g_wv; dst = g_v; bias = bv; scale = 1.f; }

    float acc[2][8][4];
    gemm_core(g_xh, W, As, Bs, acc);

    const int lane = threadIdx.x & 31, warp = threadIdx.x >> 5;
    const int wm = warp & 3, wn = warp >> 2;
#pragma unroll
    for (int im = 0; im < 2; im++) {
#pragma unroll
        for (int jn = 0; jn < 8; jn++) {
            int r  = blockIdx.y * 128 + wm * 32 + im * 16 + (lane >> 2);
            int c  = blockIdx.x * 128 + wn * 64 + jn * 8 + (lane & 3) * 2;
            int head = c >> 6, hd = c & 63;
#pragma unroll
            for (int hh = 0; hh < 2; hh++) {
                int rr = r + hh * 8;
                int b = rr >> 11, s = rr & 2047;
                float v0 = (acc[im][jn][2*hh+0] + bias[c    ]) * scale;
                float v1 = (acc[im][jn][2*hh+1] + bias[c + 1]) * scale;
                __half2* p = reinterpret_cast<__half2*>(
                    dst + ((size_t)((b * NH + head) * SEQ + s)) * HD + hd);
                *p = __floats2half2_rn(v0, v1);
            }
        }
    }
}

// ---------------- output projection: ctx @ Wo + bo -> fp32 out ----------------
__global__ __launch_bounds__(256) void gemm_out_kernel(
    const float* __restrict__ bo, float* __restrict__ out)
{
    __shared__ alignas(16) __half As[NSTG * 128 * GSA];
    __shared__ alignas(16) __half Bs[NSTG * 32 * GSB];

    float acc[2][8][4];
    gemm_core(g_ctx, g_wo, As, Bs, acc);

    const int lane = threadIdx.x & 31, warp = threadIdx.x >> 5;
    const int wm = warp & 3, wn = warp >> 2;
#pragma unroll
    for (int im = 0; im < 2; im++) {
#pragma unroll
        for (int jn = 0; jn < 8; jn++) {
            int r = blockIdx.y * 128 + wm * 32 + im * 16 + (lane >> 2);
            int c = blockIdx.x * 128 + wn * 64 + jn * 8 + (lane & 3) * 2;
#pragma unroll
            for (int hh = 0; hh < 2; hh++) {
                int rr = r + hh * 8;
                float2 v;
                v.x = acc[im][jn][2*hh+0] + bo[c];
                v.y = acc[im][jn][2*hh+1] + bo[c + 1];
                *reinterpret_cast<float2*>(out + (size_t)rr * D_MODEL + c) = v;
            }
        }
    }
}

// ---------------- flash attention: 128-query tile, 64-key iters, 3-stage pipeline ----------------
#define ASQ 72   // smem row stride (halves): conflict-free for ldmatrix
#define KITER (SEQ/64)

__global__ __launch_bounds__(256) void attn_kernel()
{
    __shared__ alignas(16) __half Qs[128 * ASQ];
    __shared__ alignas(16) __half Ks[NSTG][64 * ASQ];
    __shared__ alignas(16) __half Vs[NSTG][64 * ASQ];

    const int tid  = threadIdx.x;
    const int lane = tid & 31;
    const int warp = tid >> 5;
    const int bh   = blockIdx.y;       // b*16 + h
    const int qt   = blockIdx.x;       // query tile of 128
    const size_t base = (size_t)bh * SEQ * HD;

    // group 0: Q tile [128 x 64] = 1024 x 16B chunks
    const __half* Qp = g_q + base + (size_t)qt * 128 * HD;
#pragma unroll
    for (int i = 0; i < 4; i++) {
        int c = tid + i * 256;
        int r = c >> 3, cc = c & 7;
        cpasync16(smem_u32(Qs + r * ASQ + cc * 8), Qp + (size_t)r * HD + cc * 8);
    }
    cp_commit();

    auto loadKV = [&](int it, int st) {
        const __half* Kp = g_k + base + (size_t)it * 64 * HD;
        const __half* Vp = g_v + base + (size_t)it * 64 * HD;
#pragma unroll
        for (int i = 0; i < 2; i++) {
            int c = tid + i * 256;
            int r = c >> 3, cc = c & 7;
            cpasync16(smem_u32(&Ks[st][r * ASQ + cc * 8]), Kp + (size_t)r * HD + cc * 8);
            cpasync16(smem_u32(&Vs[st][r * ASQ + cc * 8]), Vp + (size_t)r * HD + cc * 8);
        }
    };
    // groups 1,2: KV stages 0,1
    loadKV(0, 0); cp_commit();
    loadKV(1, 1); cp_commit();

    // wait for Q (2 newer groups pending allowed), then build Q fragments
    cp_wait<2>();
    __syncthreads();

    uint32_t aq[4][4];
#pragma unroll
    for (int ks = 0; ks < 4; ks++) {
        int r    = warp * 16 + (lane & 15);
        int ccol = ks * 16 + (lane >> 4) * 8;
        ldmat_x4(aq[ks][0], aq[ks][1], aq[ks][2], aq[ks][3], smem_u32(Qs + r * ASQ + ccol));
    }

    float o[8][4];
#pragma unroll
    for (int jo = 0; jo < 8; jo++)
#pragma unroll
        for (int q = 0; q < 4; q++) o[jo][q] = 0.f;
    float m0 = -1e30f, m1 = -1e30f, l0 = 0.f, l1 = 0.f;

    for (int it = 0; it < KITER; it++) {
        // need KV group for tile it (group it+1); one newer group committed -> wait<1>
        cp_wait<1>();
        __syncthreads();   // stage ready for all; all warps done reading stage (it-1)%3

        if (it + 2 < KITER) loadKV(it + 2, (it + 2) % NSTG);
        cp_commit();       // unconditional

        const __half* ks_ = Ks[it % NSTG];
        const __half* vs_ = Vs[it % NSTG];

        // scores S = Q K^T  (Q pre-scaled by 0.125*log2e -> use exp2)
        float s[8][4];
#pragma unroll
        for (int jp = 0; jp < 4; jp++) {
#pragma unroll
            for (int q = 0; q < 4; q++) { s[2*jp][q] = 0.f; s[2*jp+1][q] = 0.f; }
#pragma unroll
            for (int ksd = 0; ksd < 4; ksd++) {
                uint32_t b0, b1, b2, b3;
                int br = jp * 16 + (lane & 7) + 8 * (lane >> 4);
                int bc = ksd * 16 + 8 * ((lane >> 3) & 1);
                ldmat_x4(b0, b1, b2, b3, smem_u32(ks_ + br * ASQ + bc));
                mma16816(s[2*jp  ], aq[ksd], b0, b1);
                mma16816(s[2*jp+1], aq[ksd], b2, b3);
            }
        }

        // online softmax (base 2)
        float mx0 = m0, mx1 = m1;
#pragma unroll
        for (int jn = 0; jn < 8; jn++) {
            mx0 = fmaxf(mx0, fmaxf(s[jn][0], s[jn][1]));
            mx1 = fmaxf(mx1, fmaxf(s[jn][2], s[jn][3]));
        }
        mx0 = fmaxf(mx0, __shfl_xor_sync(0xffffffffu, mx0, 1));
        mx0 = fmaxf(mx0, __shfl_xor_sync(0xffffffffu, mx0, 2));
        mx1 = fmaxf(mx1, __shfl_xor_sync(0xffffffffu, mx1, 1));
        mx1 = fmaxf(mx1, __shfl_xor_sync(0xffffffffu, mx1, 2));

        float alpha0 = exp2f(m0 - mx0);
        float alpha1 = exp2f(m1 - mx1);
        m0 = mx0; m1 = mx1;

        float rs0 = 0.f, rs1 = 0.f;
        uint32_t pa[4][4];
#pragma unroll
        for (int jn = 0; jn < 8; jn++) {
            float p0 = exp2f(s[jn][0] - m0), p1 = exp2f(s[jn][1] - m0);
            float p2 = exp2f(s[jn][2] - m1), p3 = exp2f(s[jn][3] - m1);
            rs0 += p0 + p1; rs1 += p2 + p3;
            int kq = jn >> 1, hi = jn & 1;
            pa[kq][2*hi + 0] = packh2(p0, p1);
            pa[kq][2*hi + 1] = packh2(p2, p3);
        }
        rs0 += __shfl_xor_sync(0xffffffffu, rs0, 1);
        rs0 += __shfl_xor_sync(0xffffffffu, rs0, 2);
        rs1 += __shfl_xor_sync(0xffffffffu, rs1, 1);
        rs1 += __shfl_xor_sync(0xffffffffu, rs1, 2);
        l0 = l0 * alpha0 + rs0;
        l1 = l1 * alpha1 + rs1;

#pragma unroll
        for (int jo = 0; jo < 8; jo++) {
            o[jo][0] *= alpha0; o[jo][1] *= alpha0;
            o[jo][2] *= alpha1; o[jo][3] *= alpha1;
        }

        // O += P @ V
#pragma unroll
        for (int ksd = 0; ksd < 4; ksd++) {
#pragma unroll
            for (int jp = 0; jp < 4; jp++) {
                uint32_t b0, b1, b2, b3;
                int br = ksd * 16 + (lane & 7) + 8 * ((lane >> 3) & 1);
                int bc = jp * 16 + 8 * (lane >> 4);
                ldmat_x4_t(b0, b1, b2, b3, smem_u32(vs_ + br * ASQ + bc));
                mma16816(o[2*jp  ], pa[ksd], b0, b1);
                mma16816(o[2*jp+1], pa[ksd], b2, b3);
            }
        }
    }

    // finalize and write ctx in [B,S,D] fp16
    float inv0 = 1.f / l0, inv1 = 1.f / l1;
    const int b = bh >> 4, h = bh & 15;
#pragma unroll
    for (int jo = 0; jo < 8; jo++) {
        int r   = qt * 128 + warp * 16 + (lane >> 2);
        int col = h * 64 + jo * 8 + (lane & 3) * 2;
        *reinterpret_cast<__half2*>(g_ctx + (size_t)(b * SEQ + r) * D_MODEL + col) =
            __floats2half2_rn(o[jo][0] * inv0, o[jo][1] * inv0);
        *reinterpret_cast<__half2*>(g_ctx + (size_t)(b * SEQ + r + 8) * D_MODEL + col) =
            __floats2half2_rn(o[jo][2] * inv1, o[jo][3] * inv1);
    }
}

// ---------------- launch ----------------
extern "C" void kernel_launch(void* const* d_in, const int* in_sizes, int n_in,
                              void* d_out, int out_size)
{
    const float* x  = (const float*)d_in[0];
    const float* Wq = (const float*)d_in[1];
    const float* bq = (const float*)d_in[2];
    const float* Wk = (const float*)d_in[3];
    const float* bk = (const float*)d_in[4];
    const float* Wv = (const float*)d_in[5];
    const float* bv = (const float*)d_in[6];
    const float* Wo = (const float*)d_in[7];
    const float* bo = (const float*)d_in[8];
    float* out = (float*)d_out;

    int total4 = (N_X + 4 * N_W) / 4;
    f2h_all<<<total4 / 256, 256>>>(x, Wq, Wk, Wv, Wo);

    gemm_qkv_kernel<<<dim3(D_MODEL / 128, ROWS / 128, 3), 256>>>(bq, bk, bv);
    attn_kernel<<<dim3(SEQ / 128, BATCH * NH), 256>>>();
    gemm_out_kernel<<<dim3(D_MODEL / 128, ROWS / 128), 256>>>(bo, out);
}

// round 10
// speedup vs baseline: 1.0568x; 1.0568x over previous
#include <cuda_runtime.h>
#include <cuda_fp16.h>
#include <cstdint>

#define D_MODEL 1024
#define SEQ     2048
#define BATCH   4
#define NH      16
#define HD      64
#define ROWS    (BATCH*SEQ)   // 8192

// ---------------- static device scratch (no allocs allowed) ----------------
__device__ alignas(16) __half g_xh [ROWS*D_MODEL];
__device__ alignas(16) __half g_wq [D_MODEL*D_MODEL];
__device__ alignas(16) __half g_wk [D_MODEL*D_MODEL];
__device__ alignas(16) __half g_wv [D_MODEL*D_MODEL];
__device__ alignas(16) __half g_wo [D_MODEL*D_MODEL];
__device__ alignas(16) __half g_q  [ROWS*D_MODEL];   // [B,H,S,HD]
__device__ alignas(16) __half g_k  [ROWS*D_MODEL];
__device__ alignas(16) __half g_v  [ROWS*D_MODEL];
__device__ alignas(16) __half g_ctx[ROWS*D_MODEL];   // [B,S,D]

// ---------------- helpers ----------------
__device__ __forceinline__ uint32_t smem_u32(const void* p) {
    return (uint32_t)__cvta_generic_to_shared(p);
}
__device__ __forceinline__ void ldmat_x4(uint32_t& r0, uint32_t& r1, uint32_t& r2, uint32_t& r3, uint32_t addr) {
    asm volatile("ldmatrix.sync.aligned.m8n8.x4.shared.b16 {%0,%1,%2,%3}, [%4];"
                 : "=r"(r0), "=r"(r1), "=r"(r2), "=r"(r3) : "r"(addr));
}
__device__ __forceinline__ void ldmat_x4_t(uint32_t& r0, uint32_t& r1, uint32_t& r2, uint32_t& r3, uint32_t addr) {
    asm volatile("ldmatrix.sync.aligned.m8n8.x4.trans.shared.b16 {%0,%1,%2,%3}, [%4];"
                 : "=r"(r0), "=r"(r1), "=r"(r2), "=r"(r3) : "r"(addr));
}
__device__ __forceinline__ void mma16816(float* c, const uint32_t* a, uint32_t b0, uint32_t b1) {
    asm volatile("mma.sync.aligned.m16n8k16.row.col.f32.f16.f16.f32 "
                 "{%0,%1,%2,%3}, {%4,%5,%6,%7}, {%8,%9}, {%0,%1,%2,%3};"
                 : "+f"(c[0]), "+f"(c[1]), "+f"(c[2]), "+f"(c[3])
                 : "r"(a[0]), "r"(a[1]), "r"(a[2]), "r"(a[3]), "r"(b0), "r"(b1));
}
__device__ __forceinline__ void cpasync16(uint32_t saddr, const void* g) {
    asm volatile("cp.async.cg.shared.global [%0], [%1], 16;" :: "r"(saddr), "l"(g));
}
__device__ __forceinline__ void cp_commit() { asm volatile("cp.async.commit_group;"); }
template<int N> __device__ __forceinline__ void cp_wait() { asm volatile("cp.async.wait_group %0;" :: "n"(N)); }

__device__ __forceinline__ uint32_t packh2(float a, float b) {
    __half2 h = __floats2half2_rn(a, b);
    return *reinterpret_cast<uint32_t*>(&h);
}

// ---------------- fused fp32 -> fp16 convert (one launch) ----------------
#define N_X  (ROWS*D_MODEL)
#define N_W  (D_MODEL*D_MODEL)
__global__ __launch_bounds__(256) void f2h_all(
    const float* __restrict__ x,  const float* __restrict__ wq,
    const float* __restrict__ wk, const float* __restrict__ wv,
    const float* __restrict__ wo)
{
    int i = (blockIdx.x * blockDim.x + threadIdx.x) * 4;
    const float* src; __half* dst; int off;
    if (i < N_X)                { src = x;  dst = g_xh; off = 0; }
    else if (i < N_X + N_W)     { src = wq; dst = g_wq; off = N_X; }
    else if (i < N_X + 2*N_W)   { src = wk; dst = g_wk; off = N_X + N_W; }
    else if (i < N_X + 3*N_W)   { src = wv; dst = g_wv; off = N_X + 2*N_W; }
    else                        { src = wo; dst = g_wo; off = N_X + 3*N_W; }
    int j = i - off;
    float4 v = *reinterpret_cast<const float4*>(src + j);
    __half2* d2 = reinterpret_cast<__half2*>(dst + j);
    d2[0] = __floats2half2_rn(v.x, v.y);
    d2[1] = __floats2half2_rn(v.z, v.w);
}

// ---------------- GEMM core: C[128x128] = A[128xK] * W[KxN], K=N=1024 ----------------
// K-chunk = 64 per stage (64 MMAs between syncs), 2-stage cp.async, R4 wait pattern.
#define GSA 72    // A smem row stride (halves), 64 data cols + pad: conflict-free
#define GSB 136   // B smem row stride (halves), 128 data cols + pad: conflict-free
#define KCH   64
#define NKCH (D_MODEL/KCH)   // 16
#define GEMM_SMEM ((2*128*GSA + 2*64*GSB) * 2)   // 71,680 bytes

__device__ __forceinline__ void gemm_core(
    const __half* __restrict__ A, const __half* __restrict__ W,
    __half* As, __half* Bs, float acc[2][8][4])
{
    const int tid  = threadIdx.x;
    const int lane = tid & 31;
    const int warp = tid >> 5;
    const int wm   = warp & 3;
    const int wn   = warp >> 2;
    const int row0 = blockIdx.y * 128;
    const int col0 = blockIdx.x * 128;

#pragma unroll
    for (int im = 0; im < 2; im++)
#pragma unroll
        for (int jn = 0; jn < 8; jn++)
#pragma unroll
            for (int q = 0; q < 4; q++) acc[im][jn][q] = 0.f;

    // A stage: 128 rows x 64 halves = 1024 x 16B chunks; B stage: 64 rows x 128 halves = 1024 chunks
    auto loadAB = [&](int kc, int st) {
#pragma unroll
        for (int i = 0; i < 4; i++) {
            int idx = tid + i * 256;
            int r = idx >> 3, cc = idx & 7;
            cpasync16(smem_u32(As + st * 128 * GSA + r * GSA + cc * 8),
                      A + (size_t)(row0 + r) * D_MODEL + kc * KCH + cc * 8);
        }
#pragma unroll
        for (int i = 0; i < 4; i++) {
            int idx = tid + i * 256;
            int r = idx >> 4, cc = idx & 15;
            cpasync16(smem_u32(Bs + st * 64 * GSB + r * GSB + cc * 8),
                      W + (size_t)(kc * KCH + r) * D_MODEL + col0 + cc * 8);
        }
    };

    loadAB(0, 0); cp_commit();

    for (int kt = 0; kt < NKCH; kt++) {
        int st = kt & 1;
        if (kt + 1 < NKCH) {
            loadAB(kt + 1, st ^ 1); cp_commit();
            cp_wait<1>();
        } else {
            cp_wait<0>();
        }
        __syncthreads();

        const __half* as = As + st * 128 * GSA;
        const __half* bs = Bs + st * 64 * GSB;

#pragma unroll
        for (int kk = 0; kk < 4; kk++) {
            uint32_t af[2][4];
#pragma unroll
            for (int im = 0; im < 2; im++) {
                int r    = wm * 32 + im * 16 + (lane & 15);
                int ccol = kk * 16 + (lane >> 4) * 8;
                ldmat_x4(af[im][0], af[im][1], af[im][2], af[im][3],
                         smem_u32(as + r * GSA + ccol));
            }
#pragma unroll
            for (int jp = 0; jp < 4; jp++) {
                uint32_t b0, b1, b2, b3;
                int br = kk * 16 + (lane & 7) + 8 * ((lane >> 3) & 1);
                int bc = wn * 64 + jp * 16 + 8 * (lane >> 4);
                ldmat_x4_t(b0, b1, b2, b3, smem_u32(bs + br * GSB + bc));
                mma16816(acc[0][2*jp  ], af[0], b0, b1);
                mma16816(acc[1][2*jp  ], af[1], b0, b1);
                mma16816(acc[0][2*jp+1], af[0], b2, b3);
                mma16816(acc[1][2*jp+1], af[1], b2, b3);
            }
        }
        __syncthreads();
    }
}

// ---------------- QKV projection: z selects W/bias/dst ----------------
// Q gets 0.125 * log2(e) folded in so attention can use exp2 directly.
#define QSCALE 0.180336879f

__global__ __launch_bounds__(256) void gemm_qkv_kernel(
    const float* __restrict__ bq, const float* __restrict__ bk, const float* __restrict__ bv)
{
    extern __shared__ __align__(16) __half sm[];
    __half* As = sm;
    __half* Bs = sm + 2 * 128 * GSA;

    const __half* W; __half* dst; const float* bias; float scale;
    if      (blockIdx.z == 0) { W = g_wq; dst = g_q; bias = bq; scale = QSCALE; }
    else if (blockIdx.z == 1) { W = g_wk; dst = g_k; bias = bk; scale = 1.f; }
    else                      { W = g_wv; dst = g_v; bias = bv; scale = 1.f; }

    float acc[2][8][4];
    gemm_core(g_xh, W, As, Bs, acc);

    const int lane = threadIdx.x & 31, warp = threadIdx.x >> 5;
    const int wm = warp & 3, wn = warp >> 2;
#pragma unroll
    for (int im = 0; im < 2; im++) {
#pragma unroll
        for (int jn = 0; jn < 8; jn++) {
            int r  = blockIdx.y * 128 + wm * 32 + im * 16 + (lane >> 2);
            int c  = blockIdx.x * 128 + wn * 64 + jn * 8 + (lane & 3) * 2;
            int head = c >> 6, hd = c & 63;
#pragma unroll
            for (int hh = 0; hh < 2; hh++) {
                int rr = r + hh * 8;
                int b = rr >> 11, s = rr & 2047;
                float v0 = (acc[im][jn][2*hh+0] + bias[c    ]) * scale;
                float v1 = (acc[im][jn][2*hh+1] + bias[c + 1]) * scale;
                __half2* p = reinterpret_cast<__half2*>(
                    dst + ((size_t)((b * NH + head) * SEQ + s)) * HD + hd);
                *p = __floats2half2_rn(v0, v1);
            }
        }
    }
}

// ---------------- output projection: ctx @ Wo + bo -> fp32 out ----------------
__global__ __launch_bounds__(256) void gemm_out_kernel(
    const float* __restrict__ bo, float* __restrict__ out)
{
    extern __shared__ __align__(16) __half sm[];
    __half* As = sm;
    __half* Bs = sm + 2 * 128 * GSA;

    float acc[2][8][4];
    gemm_core(g_ctx, g_wo, As, Bs, acc);

    const int lane = threadIdx.x & 31, warp = threadIdx.x >> 5;
    const int wm = warp & 3, wn = warp >> 2;
#pragma unroll
    for (int im = 0; im < 2; im++) {
#pragma unroll
        for (int jn = 0; jn < 8; jn++) {
            int r = blockIdx.y * 128 + wm * 32 + im * 16 + (lane >> 2);
            int c = blockIdx.x * 128 + wn * 64 + jn * 8 + (lane & 3) * 2;
#pragma unroll
            for (int hh = 0; hh < 2; hh++) {
                int rr = r + hh * 8;
                float2 v;
                v.x = acc[im][jn][2*hh+0] + bo[c];
                v.y = acc[im][jn][2*hh+1] + bo[c + 1];
                *reinterpret_cast<float2*>(out + (size_t)rr * D_MODEL + c) = v;
            }
        }
    }
}

// ---------------- flash attention: 128-query tile, 128-key stages (2x64 inner) ----------------
#define ASQ 72
#define KOUT (SEQ/128)   // 16 outer iterations
#define ATTN_SMEM ((128*ASQ + 2*128*ASQ + 2*128*ASQ) * 2)   // 92,160 bytes

__global__ __launch_bounds__(256) void attn_kernel()
{
    extern __shared__ __align__(16) __half sm[];
    __half* Qs = sm;                       // 128 x ASQ
    __half* Ks = sm + 128 * ASQ;           // 2 stages x 128 x ASQ
    __half* Vs = Ks + 2 * 128 * ASQ;       // 2 stages x 128 x ASQ

    const int tid  = threadIdx.x;
    const int lane = tid & 31;
    const int warp = tid >> 5;
    const int bh   = blockIdx.y;
    const int qt   = blockIdx.x;
    const size_t base = (size_t)bh * SEQ * HD;

    // Q tile [128 x 64] = 1024 x 16B chunks
    const __half* Qp = g_q + base + (size_t)qt * 128 * HD;
#pragma unroll
    for (int i = 0; i < 4; i++) {
        int c = tid + i * 256;
        int r = c >> 3, cc = c & 7;
        cpasync16(smem_u32(Qs + r * ASQ + cc * 8), Qp + (size_t)r * HD + cc * 8);
    }
    cp_commit();

    // K/V stage: 128 rows x 64 halves = 1024 chunks each
    auto loadKV = [&](int it, int st) {
        const __half* Kp = g_k + base + (size_t)it * 128 * HD;
        const __half* Vp = g_v + base + (size_t)it * 128 * HD;
#pragma unroll
        for (int i = 0; i < 4; i++) {
            int c = tid + i * 256;
            int r = c >> 3, cc = c & 7;
            cpasync16(smem_u32(Ks + st * 128 * ASQ + r * ASQ + cc * 8), Kp + (size_t)r * HD + cc * 8);
            cpasync16(smem_u32(Vs + st * 128 * ASQ + r * ASQ + cc * 8), Vp + (size_t)r * HD + cc * 8);
        }
    };
    loadKV(0, 0); cp_commit();

    cp_wait<1>();   // Q ready (KV group 0 may be in flight)
    __syncthreads();

    uint32_t aq[4][4];
#pragma unroll
    for (int ks = 0; ks < 4; ks++) {
        int r    = warp * 16 + (lane & 15);
        int ccol = ks * 16 + (lane >> 4) * 8;
        ldmat_x4(aq[ks][0], aq[ks][1], aq[ks][2], aq[ks][3], smem_u32(Qs + r * ASQ + ccol));
    }

    float o[8][4];
#pragma unroll
    for (int jo = 0; jo < 8; jo++)
#pragma unroll
        for (int q = 0; q < 4; q++) o[jo][q] = 0.f;
    float m0 = -1e30f, m1 = -1e30f, l0 = 0.f, l1 = 0.f;

    for (int it = 0; it < KOUT; it++) {
        int st = it & 1;
        if (it + 1 < KOUT) {
            loadKV(it + 1, st ^ 1); cp_commit();
            cp_wait<1>();
        } else {
            cp_wait<0>();
        }
        __syncthreads();

#pragma unroll
        for (int half = 0; half < 2; half++) {
            const __half* ks_ = Ks + st * 128 * ASQ + half * 64 * ASQ;
            const __half* vs_ = Vs + st * 128 * ASQ + half * 64 * ASQ;

            // scores S = Q K^T  (Q pre-scaled by 0.125*log2e -> exp2 softmax)
            float s[8][4];
#pragma unroll
            for (int jp = 0; jp < 4; jp++) {
#pragma unroll
                for (int q = 0; q < 4; q++) { s[2*jp][q] = 0.f; s[2*jp+1][q] = 0.f; }
#pragma unroll
                for (int ksd = 0; ksd < 4; ksd++) {
                    uint32_t b0, b1, b2, b3;
                    int br = jp * 16 + (lane & 7) + 8 * (lane >> 4);
                    int bc = ksd * 16 + 8 * ((lane >> 3) & 1);
                    ldmat_x4(b0, b1, b2, b3, smem_u32(ks_ + br * ASQ + bc));
                    mma16816(s[2*jp  ], aq[ksd], b0, b1);
                    mma16816(s[2*jp+1], aq[ksd], b2, b3);
                }
            }

            // online softmax (base 2)
            float mx0 = m0, mx1 = m1;
#pragma unroll
            for (int jn = 0; jn < 8; jn++) {
                mx0 = fmaxf(mx0, fmaxf(s[jn][0], s[jn][1]));
                mx1 = fmaxf(mx1, fmaxf(s[jn][2], s[jn][3]));
            }
            mx0 = fmaxf(mx0, __shfl_xor_sync(0xffffffffu, mx0, 1));
            mx0 = fmaxf(mx0, __shfl_xor_sync(0xffffffffu, mx0, 2));
            mx1 = fmaxf(mx1, __shfl_xor_sync(0xffffffffu, mx1, 1));
            mx1 = fmaxf(mx1, __shfl_xor_sync(0xffffffffu, mx1, 2));

            float alpha0 = exp2f(m0 - mx0);
            float alpha1 = exp2f(m1 - mx1);
            m0 = mx0; m1 = mx1;

            float rs0 = 0.f, rs1 = 0.f;
            uint32_t pa[4][4];
#pragma unroll
            for (int jn = 0; jn < 8; jn++) {
                float p0 = exp2f(s[jn][0] - m0), p1 = exp2f(s[jn][1] - m0);
                float p2 = exp2f(s[jn][2] - m1), p3 = exp2f(s[jn][3] - m1);
                rs0 += p0 + p1; rs1 += p2 + p3;
                int kq = jn >> 1, hi = jn & 1;
                pa[kq][2*hi + 0] = packh2(p0, p1);
                pa[kq][2*hi + 1] = packh2(p2, p3);
            }
            rs0 += __shfl_xor_sync(0xffffffffu, rs0, 1);
            rs0 += __shfl_xor_sync(0xffffffffu, rs0, 2);
            rs1 += __shfl_xor_sync(0xffffffffu, rs1, 1);
            rs1 += __shfl_xor_sync(0xffffffffu, rs1, 2);
            l0 = l0 * alpha0 + rs0;
            l1 = l1 * alpha1 + rs1;

#pragma unroll
            for (int jo = 0; jo < 8; jo++) {
                o[jo][0] *= alpha0; o[jo][1] *= alpha0;
                o[jo][2] *= alpha1; o[jo][3] *= alpha1;
            }

            // O += P @ V
#pragma unroll
            for (int ksd = 0; ksd < 4; ksd++) {
#pragma unroll
                for (int jp = 0; jp < 4; jp++) {
                    uint32_t b0, b1, b2, b3;
                    int br = ksd * 16 + (lane & 7) + 8 * ((lane >> 3) & 1);
                    int bc = jp * 16 + 8 * (lane >> 4);
                    ldmat_x4_t(b0, b1, b2, b3, smem_u32(vs_ + br * ASQ + bc));
                    mma16816(o[2*jp  ], pa[ksd], b0, b1);
                    mma16816(o[2*jp+1], pa[ksd], b2, b3);
                }
            }
        }
        __syncthreads();
    }

    // finalize and write ctx in [B,S,D] fp16
    float inv0 = 1.f / l0, inv1 = 1.f / l1;
    const int b = bh >> 4, h = bh & 15;
#pragma unroll
    for (int jo = 0; jo < 8; jo++) {
        int r   = qt * 128 + warp * 16 + (lane >> 2);
        int col = h * 64 + jo * 8 + (lane & 3) * 2;
        *reinterpret_cast<__half2*>(g_ctx + (size_t)(b * SEQ + r) * D_MODEL + col) =
            __floats2half2_rn(o[jo][0] * inv0, o[jo][1] * inv0);
        *reinterpret_cast<__half2*>(g_ctx + (size_t)(b * SEQ + r + 8) * D_MODEL + col) =
            __floats2half2_rn(o[jo][2] * inv1, o[jo][3] * inv1);
    }
}

// ---------------- launch ----------------
extern "C" void kernel_launch(void* const* d_in, const int* in_sizes, int n_in,
                              void* d_out, int out_size)
{
    const float* x  = (const float*)d_in[0];
    const float* Wq = (const float*)d_in[1];
    const float* bq = (const float*)d_in[2];
    const float* Wk = (const float*)d_in[3];
    const float* bk = (const float*)d_in[4];
    const float* Wv = (const float*)d_in[5];
    const float* bv = (const float*)d_in[6];
    const float* Wo = (const float*)d_in[7];
    const float* bo = (const float*)d_in[8];
    float* out = (float*)d_out;

    cudaFuncSetAttribute(gemm_qkv_kernel, cudaFuncAttributeMaxDynamicSharedMemorySize, GEMM_SMEM);
    cudaFuncSetAttribute(gemm_out_kernel, cudaFuncAttributeMaxDynamicSharedMemorySize, GEMM_SMEM);
    cudaFuncSetAttribute(attn_kernel,     cudaFuncAttributeMaxDynamicSharedMemorySize, ATTN_SMEM);

    int total4 = (N_X + 4 * N_W) / 4;
    f2h_all<<<total4 / 256, 256>>>(x, Wq, Wk, Wv, Wo);

    gemm_qkv_kernel<<<dim3(D_MODEL / 128, ROWS / 128, 3), 256, GEMM_SMEM>>>(bq, bk, bv);
    attn_kernel<<<dim3(SEQ / 128, BATCH * NH), 256, ATTN_SMEM>>>();
    gemm_out_kernel<<<dim3(D_MODEL / 128, ROWS / 128), 256, GEMM_SMEM>>>(bo, out);
}